// round 8
// baseline (speedup 1.0000x reference)
#include <cuda_runtime.h>
#include <cuda_bf16.h>
#include <math_constants.h>
#include <cstdint>

// ---------------------------------------------------------------------------
// att = softmax( MLP3(concat(node1, u_rep)) ), N = 200000, d = 128.
// Single fused persistent kernel, 512 threads (16 warps, 4Mx4N warp grid):
//   - u_rep half of layer 1 folded into fp32 cvec (computed in-kernel)
//   - weights split bf16 hi/lo in-kernel into fragment-packed smem
//   - GEMMs via bf16x3 on mma.sync:  D = Ah*Bh + Al*Bh + Ah*Bl
//   - logits kept in registers; grid-wide barrier; fused softmax + normalize
// ---------------------------------------------------------------------------

#define EMB     128
#define TILE    128
#define LMAX    16      // max tiles per CTA (ceil(1563/148) = 11)
#define GMAX    256
#define THREADS 512

// ---- smem layout (bytes) ----
#define OFF_W1   0        // 64KB: W1 frag-packed, 16B/frag = [bh0 bh1 bl0 bl1]
#define OFF_W2   65536    // 64KB
#define OFF_AH   131072   // 32KB
#define OFF_AL   163840   // 32KB
#define OFF_CVEC 196608
#define OFF_B2   197120
#define OFF_W3   197632
#define OFF_PART 198144   // 2KB (4 x 128 floats)
#define OFF_RED  200192   // 64B (16 floats)
#define SMEM_TOTAL 200256

// ---------------- device scratch ----------------
__device__ float        g_ctamax[GMAX];
__device__ float        g_ctasum[GMAX];
__device__ unsigned int g_bar;    // zero-init; reset in-kernel each run
__device__ unsigned int g_done;

__device__ __forceinline__ uint32_t b2u(__nv_bfloat162 h) {
    return *reinterpret_cast<uint32_t*>(&h);
}

// mma.sync m16n8k16 bf16, fp32 accumulate in place (sm_80+ PTX)
__device__ __forceinline__ void mma_bf16(float* c, const uint32_t* a,
                                         uint32_t b0, uint32_t b1) {
    asm volatile("mma.sync.aligned.m16n8k16.row.col.f32.bf16.bf16.f32 "
        "{%0,%1,%2,%3}, {%4,%5,%6,%7}, {%8,%9}, {%0,%1,%2,%3};"
        : "+f"(c[0]), "+f"(c[1]), "+f"(c[2]), "+f"(c[3])
        : "r"(a[0]), "r"(a[1]), "r"(a[2]), "r"(a[3]), "r"(b0), "r"(b1));
}

// Weight fragment address (byte offset of the hi element; lo at +8).
// B[n][k] "col" operand of m16n8k16: lane=(n&7)*4+((k>>1)&3),
// sub = ((k>>3)&1)*2 + (k&1); 16B per (key=((n>>3)*8+(k>>4))*32+lane).
__device__ __forceinline__ int widx_hi(int n, int k) {
    int key = (((n >> 3) * 8 + (k >> 4)) * 32 + (n & 7) * 4 + ((k >> 1) & 3));
    int sub = ((k >> 3) & 1) * 2 + (k & 1);
    return key * 16 + sub * 2;
}

// ---------------------------------------------------------------------------
// One 128x128x128 layer slice: acc += Ah*Wh + Al*Wh + Ah*Wl  (bf16x3)
// Warp owns rows [warpM*32, +32), cols [warpN*32, +32).
// ---------------------------------------------------------------------------
__device__ __forceinline__ void run_layer(char* smc, int offW,
                                          float acc[2][4][4],
                                          int warpM, int warpN, int lane)
{
    #pragma unroll
    for (int ks = 0; ks < 8; ks++) {
        uint4 ah[2], al[2];
        #pragma unroll
        for (int mt = 0; mt < 2; mt++) {
            int mta  = warpM * 2 + mt;
            int aoff = ((mta * 8 + ks) * 32 + lane) * 16;
            ah[mt] = *(const uint4*)(smc + OFF_AH + aoff);
            al[mt] = *(const uint4*)(smc + OFF_AL + aoff);
        }
        #pragma unroll
        for (int j = 0; j < 4; j++) {
            int ntg  = warpN * 4 + j;
            int boff = ((ntg * 8 + ks) * 32 + lane) * 16;
            uint4 b = *(const uint4*)(smc + offW + boff);   // bh.x bh.y bl.x bl.y
            #pragma unroll
            for (int mt = 0; mt < 2; mt++) {
                mma_bf16(acc[mt][j], (const uint32_t*)&ah[mt], b.x, b.y);
                mma_bf16(acc[mt][j], (const uint32_t*)&al[mt], b.x, b.y);
                mma_bf16(acc[mt][j], (const uint32_t*)&ah[mt], b.z, b.w);
            }
        }
    }
}

// prefetch one 128-row node1 tile into registers (8 float4 per thread)
__device__ __forceinline__ void pfetch(const float4* __restrict__ n4, int base,
                                       int N, int wid, int lane, float4 pf[8])
{
    #pragma unroll
    for (int it = 0; it < 8; it++) {
        float4 v = make_float4(0.f, 0.f, 0.f, 0.f);
        if (base >= 0) {
            int gr = base + it * 16 + wid;
            if (gr < N) v = n4[(size_t)gr * 32 + lane];
        }
        pf[it] = v;
    }
}

// ---------------------------------------------------------------------------
__global__ __launch_bounds__(THREADS, 1)
void k_fused(const float* __restrict__ node1, const float* __restrict__ u_rep,
             const float* __restrict__ W1, const float* __restrict__ b1,
             const float* __restrict__ W2, const float* __restrict__ b2g,
             const float* __restrict__ w3g, const float* __restrict__ b3g,
             float* __restrict__ out, int N, int ntiles)
{
    extern __shared__ char smc[];
    const int tid   = threadIdx.x;
    const int wid   = tid >> 5;      // 0..15
    const int lane  = tid & 31;
    const int warpM = wid & 3;       // 4-way M split (32 rows)
    const int warpN = wid >> 2;      // 4-way N split (32 cols)
    const int g     = lane >> 2;
    const int t     = lane & 3;
    const int bid   = blockIdx.x;
    const unsigned G = gridDim.x;

    float* s_cvec = (float*)(smc + OFF_CVEC);
    float* s_b2   = (float*)(smc + OFF_B2);
    float* s_w3   = (float*)(smc + OFF_W3);
    float* s_part = (float*)(smc + OFF_PART);
    float* s_red  = (float*)(smc + OFF_RED);

    // ---- in-kernel weight split (bf16 hi/lo), fragment-packed ----
    for (int i = tid; i < EMB * EMB; i += THREADS) {
        int n = i >> 7, k = i & 127;
        int off = widx_hi(n, k);
        float w1 = W1[n * 256 + k];                   // node1 half of W1
        __nv_bfloat16 h1 = __float2bfloat16(w1);
        *(__nv_bfloat16*)(smc + OFF_W1 + off)     = h1;
        *(__nv_bfloat16*)(smc + OFF_W1 + off + 8) =
            __float2bfloat16(w1 - __bfloat162float(h1));
        float w2 = W2[n * 128 + k];
        __nv_bfloat16 h2 = __float2bfloat16(w2);
        *(__nv_bfloat16*)(smc + OFF_W2 + off)     = h2;
        *(__nv_bfloat16*)(smc + OFF_W2 + off + 8) =
            __float2bfloat16(w2 - __bfloat162float(h2));
    }
    // cvec = u_rep @ W1b^T + b1 (fp32, exact path)
    if (tid < 128) {
        float acc = b1[tid];
        const float* w = W1 + tid * 256 + 128;
        #pragma unroll 8
        for (int kk = 0; kk < 128; kk++) acc += u_rep[kk] * w[kk];
        s_cvec[tid] = acc;
        s_b2[tid]   = b2g[tid];
        s_w3[tid]   = w3g[tid];
    }
    __syncthreads();

    const float fb3 = b3g[0];
    const float4* n4 = (const float4*)node1;

    const int nt = (ntiles > bid) ? (ntiles - 1 - bid) / (int)G + 1 : 0;
    float lg[LMAX];           // per-thread logits (tid<128)
    float runmax = -CUDART_INF_F;

    float4 pf[8];
    pfetch(n4, (0 < nt) ? (bid * TILE) : -1, N, wid, lane, pf);

    for (int kt = 0; kt < nt; kt++) {
        const int tile = bid + kt * (int)G;
        const int base = tile * TILE;

        // ---- stage: split prefetched fp32 -> bf16 hi/lo, fragment-packed ----
        #pragma unroll
        for (int it = 0; it < 8; it++) {
            float4 v = pf[it];
            int r = it * 16 + wid;     // row in tile
            int q = lane;              // float4 col index (k = 4q)
            __nv_bfloat162 h01 = __floats2bfloat162_rn(v.x, v.y);
            __nv_bfloat162 h23 = __floats2bfloat162_rn(v.z, v.w);
            __nv_bfloat162 l01 = __floats2bfloat162_rn(v.x - __bfloat162float(h01.x),
                                                       v.y - __bfloat162float(h01.y));
            __nv_bfloat162 l23 = __floats2bfloat162_rn(v.z - __bfloat162float(h23.x),
                                                       v.w - __bfloat162float(h23.y));
            int mt = r >> 4, gg = r & 7, half = (r >> 3) & 1;
            int ks = q >> 2, khi = (q >> 1) & 1;
            int t0 = (2 * q) & 3, t1 = (2 * q + 1) & 3;
            int cb = ((mt * 8 + ks) * 32 + gg * 4) * 16 + half * 4 + khi * 8;
            *(uint32_t*)(smc + OFF_AH + cb + t0 * 16) = b2u(h01);
            *(uint32_t*)(smc + OFF_AL + cb + t0 * 16) = b2u(l01);
            *(uint32_t*)(smc + OFF_AH + cb + t1 * 16) = b2u(h23);
            *(uint32_t*)(smc + OFF_AL + cb + t1 * 16) = b2u(l23);
        }
        __syncthreads();

        // ---- layer 1 ----
        float acc[2][4][4];
        #pragma unroll
        for (int mt = 0; mt < 2; mt++)
            #pragma unroll
            for (int j = 0; j < 4; j++)
                #pragma unroll
                for (int e = 0; e < 4; e++) acc[mt][j][e] = 0.f;

        run_layer(smc, OFF_W1, acc, warpM, warpN, lane);
        __syncthreads();                 // A consumed; may be rewritten

        // prefetch next tile while epilogue1 + layer2 run
        {
            int tile2 = bid + (kt + 1) * (int)G;
            pfetch(n4, (tile2 < ntiles) ? tile2 * TILE : -1, N, wid, lane, pf);
        }

        // ---- epilogue 1: relu(C + cvec) -> bf16 hi/lo back into A tiles ----
        #pragma unroll
        for (int mt = 0; mt < 2; mt++) {
            int mta = warpM * 2 + mt;
            #pragma unroll
            for (int j = 0; j < 4; j++) {
                int ntg  = warpN * 4 + j;
                int col0 = ntg * 8 + t * 2;
                float* c = acc[mt][j];
                float v0 = fmaxf(c[0] + s_cvec[col0],     0.f);
                float v1 = fmaxf(c[1] + s_cvec[col0 + 1], 0.f);
                float v2 = fmaxf(c[2] + s_cvec[col0],     0.f);
                float v3 = fmaxf(c[3] + s_cvec[col0 + 1], 0.f);
                __nv_bfloat162 h01 = __floats2bfloat162_rn(v0, v1);
                __nv_bfloat162 h23 = __floats2bfloat162_rn(v2, v3);
                __nv_bfloat162 l01 = __floats2bfloat162_rn(v0 - __bfloat162float(h01.x),
                                                           v1 - __bfloat162float(h01.y));
                __nv_bfloat162 l23 = __floats2bfloat162_rn(v2 - __bfloat162float(h23.x),
                                                           v3 - __bfloat162float(h23.y));
                int cb = ((mta * 8 + (ntg >> 1)) * 32 + g * 4 + t) * 16 + (ntg & 1) * 8;
                *(uint32_t*)(smc + OFF_AH + cb)     = b2u(h01);   // rows g   (half 0)
                *(uint32_t*)(smc + OFF_AL + cb)     = b2u(l01);
                *(uint32_t*)(smc + OFF_AH + cb + 4) = b2u(h23);   // rows g+8 (half 1)
                *(uint32_t*)(smc + OFF_AL + cb + 4) = b2u(l23);
                c[0] = c[1] = c[2] = c[3] = 0.f;
            }
        }
        __syncthreads();

        // ---- layer 2 ----
        run_layer(smc, OFF_W2, acc, warpM, warpN, lane);

        // ---- epilogue 2: relu(C + b2) dot w3 -> per-row partials ----
        float sp[2][2] = {{0.f, 0.f}, {0.f, 0.f}};   // [mt][half]
        #pragma unroll
        for (int mt = 0; mt < 2; mt++) {
            #pragma unroll
            for (int j = 0; j < 4; j++) {
                int ntg  = warpN * 4 + j;
                int col0 = ntg * 8 + t * 2;
                float* c = acc[mt][j];
                float w0 = s_w3[col0], w1 = s_w3[col0 + 1];
                float bb0 = s_b2[col0], bb1 = s_b2[col0 + 1];
                sp[mt][0] += fmaxf(c[0] + bb0, 0.f) * w0
                           + fmaxf(c[1] + bb1, 0.f) * w1;
                sp[mt][1] += fmaxf(c[2] + bb0, 0.f) * w0
                           + fmaxf(c[3] + bb1, 0.f) * w1;
            }
        }
        #pragma unroll
        for (int off = 1; off < 4; off <<= 1) {
            #pragma unroll
            for (int mt = 0; mt < 2; mt++) {
                sp[mt][0] += __shfl_xor_sync(0xffffffffu, sp[mt][0], off);
                sp[mt][1] += __shfl_xor_sync(0xffffffffu, sp[mt][1], off);
            }
        }
        if (t == 0) {
            #pragma unroll
            for (int mt = 0; mt < 2; mt++) {
                int rbase = warpM * 32 + mt * 16;
                s_part[warpN * 128 + rbase + g]     = sp[mt][0];
                s_part[warpN * 128 + rbase + 8 + g] = sp[mt][1];
            }
        }
        __syncthreads();

        if (tid < 128) {
            int gr = base + tid;
            float v = s_part[tid] + s_part[128 + tid] + s_part[256 + tid]
                    + s_part[384 + tid] + fb3;
            lg[kt] = v;
            if (gr < N) runmax = fmaxf(runmax, v);
        }
        __syncthreads();
    }

    // ---- phase-1 end: per-CTA max ----
    float m = runmax;
    #pragma unroll
    for (int s = 16; s > 0; s >>= 1) m = fmaxf(m, __shfl_xor_sync(0xffffffffu, m, s));
    if (lane == 0) s_red[wid] = m;
    __syncthreads();
    if (tid == 0) {
        float mx = s_red[0];
        #pragma unroll
        for (int i = 1; i < 16; i++) mx = fmaxf(mx, s_red[i]);
        g_ctamax[bid] = mx;
        __threadfence();
        atomicAdd(&g_bar, 1u);
        while (atomicAdd(&g_bar, 0u) < G) __nanosleep(64);
        __threadfence();
    }
    __syncthreads();

    // ---- phase 2: global max (deterministic serial), exp, per-CTA sum ----
    float gmax = g_ctamax[0];
    for (unsigned i = 1; i < G; i++) gmax = fmaxf(gmax, g_ctamax[i]);

    float psum = 0.f;
    if (tid < 128) {
        for (int kt = 0; kt < nt; kt++) {
            int gr = (bid + kt * (int)G) * TILE + tid;
            if (gr < N) {
                float e = __expf(lg[kt] - gmax);
                lg[kt] = e;
                psum += e;
            }
        }
    }
    #pragma unroll
    for (int s = 16; s > 0; s >>= 1) psum += __shfl_xor_sync(0xffffffffu, psum, s);
    if (lane == 0) s_red[wid] = psum;
    __syncthreads();
    if (tid == 0) {
        float sm = 0.f;
        #pragma unroll
        for (int i = 0; i < 16; i++) sm += s_red[i];
        g_ctasum[bid] = sm;
        __threadfence();
        atomicAdd(&g_bar, 1u);
        while (atomicAdd(&g_bar, 0u) < 2u * G) __nanosleep(64);
        __threadfence();
    }
    __syncthreads();

    // ---- phase 3: total sum (deterministic serial), normalize, write ----
    float tot = 0.f;
    for (unsigned i = 0; i < G; i++) tot += g_ctasum[i];
    const float inv = 1.f / tot;

    if (tid < 128) {
        for (int kt = 0; kt < nt; kt++) {
            int gr = (bid + kt * (int)G) * TILE + tid;
            if (gr < N) out[gr] = lg[kt] * inv;
        }
    }

    // ---- reset barrier state for next graph replay ----
    __syncthreads();
    if (tid == 0) {
        unsigned d = atomicAdd(&g_done, 1u);
        if (d == G - 1u) {
            atomicExch(&g_bar, 0u);
            atomicExch(&g_done, 0u);
            __threadfence();
        }
    }
}

// ---------------------------------------------------------------------------
extern "C" void kernel_launch(void* const* d_in, const int* in_sizes, int n_in,
                              void* d_out, int out_size)
{
    const float* node1 = (const float*)d_in[0];
    const float* u_rep = (const float*)d_in[1];

    // inputs: node1, u_rep, [num_neighs], W1, b1, W2, b2, W3, b3
    int wi = (n_in >= 9) ? 2 + (n_in - 8) : 2;
    if (in_sizes[wi] != 128 * 256) {
        for (int i = 2; i + 5 < n_in; i++)
            if (in_sizes[i] == 128 * 256) { wi = i; break; }
    }
    const float* W1 = (const float*)d_in[wi + 0];
    const float* b1 = (const float*)d_in[wi + 1];
    const float* W2 = (const float*)d_in[wi + 2];
    const float* b2 = (const float*)d_in[wi + 3];
    const float* W3 = (const float*)d_in[wi + 4];
    const float* b3 = (const float*)d_in[wi + 5];
    float* out = (float*)d_out;

    const int N      = in_sizes[0] / EMB;
    const int ntiles = (N + TILE - 1) / TILE;

    int nsm = 0;
    cudaDeviceGetAttribute(&nsm, cudaDevAttrMultiProcessorCount, 0);
    if (nsm <= 0) nsm = 148;
    int grid = ntiles < nsm ? ntiles : nsm;
    if (grid > GMAX) grid = GMAX;

    cudaFuncSetAttribute(k_fused, cudaFuncAttributeMaxDynamicSharedMemorySize,
                         SMEM_TOTAL);
    k_fused<<<grid, THREADS, SMEM_TOTAL>>>(node1, u_rep, W1, b1, W2, b2, W3, b3,
                                           out, N, ntiles);
}